// round 16
// baseline (speedup 1.0000x reference)
#include <cuda_runtime.h>
#include <cuda_fp16.h>
#include <math.h>

#define DH 256          // feature dim (D == H == 256)
#define AOUT 8
#define MAXN 20000
#define MAXE 320000
#define MAXT (MAXN + MAXE)
#define SCANB 256       // scan1/scan3 block size

// ---------------- device scratch (no allocations allowed) ----------------
__device__ __half   g_obsh[(size_t)MAXN * DH];   // fp16 obs; reused as gemm3 out
__device__ __half   g_h1[(size_t)MAXN * DH];     // gemm outputs (fp16)
__device__ __half   g_h2[(size_t)MAXN * DH];
__device__ __half   g_w1h[DH * DH];              // weights, fp16, TRANSPOSED [n][k]
__device__ __half   g_w2h[DH * DH];
__device__ __half   g_wm1h[DH * DH];
__device__ float    g_as1[MAXN];
__device__ float    g_ad1[MAXN];
__device__ float    g_as2[MAXN];
__device__ float    g_ad2[MAXN];
__device__ int      g_rowptr[MAXN + 1];
__device__ int      g_cursor[MAXN];
__device__ int      g_partial[MAXN];      // exclusive within-block prefixes
__device__ int      g_blocksums[128];
__device__ int      g_blockoff[128];
__device__ int      g_perm[MAXT];         // src node ids grouped by dst

// ---------------- prep: weights->fp16^T, score-acc zeros, obs->fp16 ----------------
__global__ void k_prep(const float* __restrict__ W1,
                       const float* __restrict__ W2,
                       const float* __restrict__ Wm1,
                       const float* __restrict__ obs,
                       int N, int obs8)
{
    int i = blockIdx.x * blockDim.x + threadIdx.x;
    if (i < 65536) {
        int n = i >> 8, k = i & 255;                 // write coalesced in [n][k]
        g_w1h[i] = __float2half(W1[k * DH + n]);
    } else if (i < 2 * 65536) {
        int j = i - 65536;
        int n = j >> 8, k = j & 255;
        g_w2h[j] = __float2half(W2[k * DH + n]);
    } else if (i < 3 * 65536) {
        int j = i - 2 * 65536;
        int n = j >> 8, k = j & 255;
        g_wm1h[j] = __float2half(Wm1[k * DH + n]);
    } else if (i < 3 * 65536 + N) {
        int j = i - 3 * 65536;
        g_as1[j] = 0.f; g_ad1[j] = 0.f;
        g_as2[j] = 0.f; g_ad2[j] = 0.f;
    } else {
        int q = i - 3 * 65536 - N;
        if (q < obs8) {
            const float4* src = (const float4*)(obs) + q * 2;
            float4 v0 = src[0], v1 = src[1];
            __half2 h0 = __floats2half2_rn(v0.x, v0.y);
            __half2 h1 = __floats2half2_rn(v0.z, v0.w);
            __half2 h2 = __floats2half2_rn(v1.x, v1.y);
            __half2 h3 = __floats2half2_rn(v1.z, v1.w);
            uint4 pack;
            pack.x = *(unsigned*)&h0; pack.y = *(unsigned*)&h1;
            pack.z = *(unsigned*)&h2; pack.w = *(unsigned*)&h3;
            ((uint4*)g_obsh)[q] = pack;
        }
    }
}

// ---------------- CSR build (self-loops handled implicitly) ----------------
__global__ void k_zero(int N) {
    int i = blockIdx.x * blockDim.x + threadIdx.x;
    if (i < N) g_cursor[i] = 0;
}

__global__ void k_count(const int* __restrict__ ei, int E) {
    int q = blockIdx.x * blockDim.x + threadIdx.x;
    if (q * 4 >= E) return;
    int4 d4 = *(const int4*)(ei + E + q * 4);
    atomicAdd(&g_cursor[d4.x], 1);
    atomicAdd(&g_cursor[d4.y], 1);
    atomicAdd(&g_cursor[d4.z], 1);
    atomicAdd(&g_cursor[d4.w], 1);
}

// two-level scan: scan1 per-block, scan2 block sums, scan3 emit
__global__ void k_scan1(int N) {
    int i = blockIdx.x * SCANB + threadIdx.x;
    int v = (i < N) ? (g_cursor[i] + 1) : 0;      // +1 self-loop
    int lane = threadIdx.x & 31, w = threadIdx.x >> 5;
    int x = v;
#pragma unroll
    for (int o = 1; o < 32; o <<= 1) {
        int t = __shfl_up_sync(0xffffffffu, x, o);
        if (lane >= o) x += t;
    }
    __shared__ int wsum[8];
    if (lane == 31) wsum[w] = x;
    __syncthreads();
    if (w == 0) {
        int y = (lane < 8) ? wsum[lane] : 0;
#pragma unroll
        for (int o = 1; o < 8; o <<= 1) {
            int t = __shfl_up_sync(0xffffffffu, y, o);
            if (lane >= o) y += t;
        }
        if (lane < 8) wsum[lane] = y;
    }
    __syncthreads();
    int incl = x + (w > 0 ? wsum[w - 1] : 0);
    if (i < N) g_partial[i] = incl - v;           // exclusive prefix in block
    if (threadIdx.x == SCANB - 1) g_blocksums[blockIdx.x] = incl;
}

__global__ void k_scan2(int nb) {   // 1 block, 128 threads; nb <= 128
    int tid = threadIdx.x;
    int v = (tid < nb) ? g_blocksums[tid] : 0;
    int lane = tid & 31, w = tid >> 5;
    int x = v;
#pragma unroll
    for (int o = 1; o < 32; o <<= 1) {
        int t = __shfl_up_sync(0xffffffffu, x, o);
        if (lane >= o) x += t;
    }
    __shared__ int ws[4];
    if (lane == 31) ws[w] = x;
    __syncthreads();
    if (w == 0) {
        int y = (lane < 4) ? ws[lane] : 0;
#pragma unroll
        for (int o = 1; o < 4; o <<= 1) {
            int t = __shfl_up_sync(0xffffffffu, y, o);
            if (lane >= o) y += t;
        }
        if (lane < 4) ws[lane] = y;
    }
    __syncthreads();
    int incl = x + (w > 0 ? ws[w - 1] : 0);
    if (tid < nb) g_blockoff[tid] = incl - v;     // exclusive block offset
}

__global__ void k_scan3(int N) {
    int i = blockIdx.x * SCANB + threadIdx.x;
    if (i >= N) return;
    int c = g_cursor[i];                          // original degree
    int run = g_partial[i] + g_blockoff[blockIdx.x];
    g_rowptr[i] = run;
    g_perm[run] = i;                              // self-loop at group head
    g_cursor[i] = run + 1;                        // scatter cursor
    if (i == N - 1) g_rowptr[N] = run + c + 1;
}

__global__ void k_scatter(const int* __restrict__ ei, int E) {
    int q = blockIdx.x * blockDim.x + threadIdx.x;
    int base = q * 4;
    if (base >= E) return;
    if (((E & 3) == 0) && base + 3 < E) {
        int4 s4 = *(const int4*)(ei + base);
        int4 d4 = *(const int4*)(ei + E + base);
        g_perm[atomicAdd(&g_cursor[d4.x], 1)] = s4.x;
        g_perm[atomicAdd(&g_cursor[d4.y], 1)] = s4.y;
        g_perm[atomicAdd(&g_cursor[d4.z], 1)] = s4.z;
        g_perm[atomicAdd(&g_cursor[d4.w], 1)] = s4.w;
    } else {
        for (int e = base; e < E && e < base + 4; e++) {
            int s = ei[e], d = ei[E + e];
            g_perm[atomicAdd(&g_cursor[d], 1)] = s;
        }
    }
}

// ---------------- fp16 tensor-core GEMM: C[M,256] = A[M,256] @ B^T ----------------
// A fp16 [M][K] row-major; B fp16 [N][K] row-major (pre-transposed weights).
// CTA 64x128, BK=32, 4 warps (each 32x64), mma.m16n8k16, ldmatrix fragment loads.
#define GBM 64
#define GBN 128
#define GBK 32
#define ASTRH 40     // 32 + 8 pad halves (80B row; ldmatrix conflict-free)
#define BSTRH 40
#define ASZH (GBM * ASTRH)     // 2560 halves
#define BSZH (GBN * BSTRH)     // 5120 halves
#define NSTAGE 3
#define SMEM_GEMM (NSTAGE * (ASZH + BSZH) * 2)   // 46080 bytes

__global__ __launch_bounds__(128, 4) void k_gemm_f16(
    const __half* __restrict__ A, const __half* __restrict__ Bt,
    __half* __restrict__ Ch, int M,
    const float* __restrict__ bias, int act,
    const float* __restrict__ asrc, const float* __restrict__ adst,
    float* as_out, float* ad_out)
{
    extern __shared__ __half smh[];
    __half* As = smh;                      // [NSTAGE][GBM][ASTRH]
    __half* Bs = smh + NSTAGE * ASZH;      // [NSTAGE][GBN][BSTRH]

    const int tid = threadIdx.x;
    const int warpId = tid >> 5, lane = tid & 31;
    const int gid = lane >> 2, tg = lane & 3;
    const int wm = warpId >> 1, wn = warpId & 1;    // 2x2 warp grid
    const int rowBlk = blockIdx.y * GBM;
    const int colBlk = blockIdx.x * GBN;

    const int l7 = lane & 7;
    const int sel8  = (lane & 8)  ? 8 : 0;
    const int sel16 = (lane & 16) ? 8 : 0;

    float c[2][8][4];
#pragma unroll
    for (int mt = 0; mt < 2; mt++)
#pragma unroll
        for (int nt = 0; nt < 8; nt++)
#pragma unroll
            for (int q = 0; q < 4; q++) c[mt][nt][q] = 0.f;

    auto issue = [&](int buf, int k0) {
#pragma unroll
        for (int i = 0; i < 2; i++) {           // A: 64 rows x 4 chunks(16B)
            int f = tid + i * 128;
            int r = f >> 2, ch = (f & 3) << 3;
            int grow = rowBlk + r;
            const __half* src = A + (size_t)grow * DH + k0 + ch;
            unsigned dst = (unsigned)__cvta_generic_to_shared(&As[buf * ASZH + r * ASTRH + ch]);
            int sz = (grow < M) ? 16 : 0;
            asm volatile("cp.async.cg.shared.global [%0], [%1], 16, %2;\n"
                         :: "r"(dst), "l"(src), "r"(sz));
        }
#pragma unroll
        for (int i = 0; i < 4; i++) {           // B: 128 rows(n) x 4 chunks
            int f = tid + i * 128;
            int n = f >> 2, ch = (f & 3) << 3;
            const __half* src = Bt + (size_t)(colBlk + n) * DH + k0 + ch;
            unsigned dst = (unsigned)__cvta_generic_to_shared(&Bs[buf * BSZH + n * BSTRH + ch]);
            asm volatile("cp.async.cg.shared.global [%0], [%1], 16;\n"
                         :: "r"(dst), "l"(src));
        }
        asm volatile("cp.async.commit_group;\n");
    };

    auto compute = [&](int buf) {
        unsigned a[2][2][4];
#pragma unroll
        for (int ks = 0; ks < 2; ks++) {
            const int kk = ks * 16;
#pragma unroll
            for (int mt = 0; mt < 2; mt++) {
                int row = wm * 32 + mt * 16 + l7 + sel8;
                unsigned ad = (unsigned)__cvta_generic_to_shared(
                    &As[buf * ASZH + row * ASTRH + kk + sel16]);
                asm volatile(
                    "ldmatrix.sync.aligned.m8n8.x4.shared.b16 {%0,%1,%2,%3}, [%4];\n"
                    : "=r"(a[ks][mt][0]), "=r"(a[ks][mt][1]),
                      "=r"(a[ks][mt][2]), "=r"(a[ks][mt][3])
                    : "r"(ad));
            }
        }
#pragma unroll
        for (int ks = 0; ks < 2; ks++) {
            const int kk = ks * 16;
            unsigned b[8][2];
#pragma unroll
            for (int p = 0; p < 4; p++) {
                int nrow = wn * 64 + p * 16 + sel16 + l7;
                unsigned ad = (unsigned)__cvta_generic_to_shared(
                    &Bs[buf * BSZH + nrow * BSTRH + kk + sel8]);
                asm volatile(
                    "ldmatrix.sync.aligned.m8n8.x4.shared.b16 {%0,%1,%2,%3}, [%4];\n"
                    : "=r"(b[2 * p][0]), "=r"(b[2 * p][1]),
                      "=r"(b[2 * p + 1][0]), "=r"(b[2 * p + 1][1])
                    : "r"(ad));
            }
#pragma unroll
            for (int mt = 0; mt < 2; mt++)
#pragma unroll
                for (int nt = 0; nt < 8; nt++)
                    asm volatile(
                        "mma.sync.aligned.m16n8k16.row.col.f32.f16.f16.f32 "
                        "{%0,%1,%2,%3}, {%4,%5,%6,%7}, {%8,%9}, {%0,%1,%2,%3};\n"
                        : "+f"(c[mt][nt][0]), "+f"(c[mt][nt][1]),
                          "+f"(c[mt][nt][2]), "+f"(c[mt][nt][3])
                        : "r"(a[ks][mt][0]), "r"(a[ks][mt][1]),
                          "r"(a[ks][mt][2]), "r"(a[ks][mt][3]),
                          "r"(b[nt][0]), "r"(b[nt][1]));
        }
    };

    issue(0, 0);
    issue(1, GBK);
#pragma unroll
    for (int it = 0; it < DH / GBK; it++) {
        if (it < DH / GBK - 1)
            asm volatile("cp.async.wait_group 1;\n");
        else
            asm volatile("cp.async.wait_group 0;\n");
        __syncthreads();
        if (it + 2 < DH / GBK) issue((it + 2) % NSTAGE, (it + 2) * GBK);
        compute(it % NSTAGE);
    }

    // ---- fused attention scores (layers 1 & 2; fp32 accumulators) ----
    if (asrc) {
#pragma unroll
        for (int mt = 0; mt < 2; mt++) {
#pragma unroll
            for (int i = 0; i < 2; i++) {
                float s = 0.f, d = 0.f;
#pragma unroll
                for (int nt = 0; nt < 8; nt++) {
                    int col = colBlk + wn * 64 + nt * 8 + tg * 2;
                    s += c[mt][nt][i * 2] * asrc[col] + c[mt][nt][i * 2 + 1] * asrc[col + 1];
                    d += c[mt][nt][i * 2] * adst[col] + c[mt][nt][i * 2 + 1] * adst[col + 1];
                }
                s += __shfl_xor_sync(0xffffffffu, s, 1);
                s += __shfl_xor_sync(0xffffffffu, s, 2);
                d += __shfl_xor_sync(0xffffffffu, d, 1);
                d += __shfl_xor_sync(0xffffffffu, d, 2);
                int row = rowBlk + wm * 32 + mt * 16 + gid + i * 8;
                if (tg == 0 && row < M) {
                    atomicAdd(&as_out[row], s);
                    atomicAdd(&ad_out[row], d);
                }
            }
        }
    }

    // ---- store C (fp16) ----
#pragma unroll
    for (int mt = 0; mt < 2; mt++) {
#pragma unroll
        for (int i = 0; i < 2; i++) {
            int row = rowBlk + wm * 32 + mt * 16 + gid + i * 8;
            if (row >= M) continue;
#pragma unroll
            for (int nt = 0; nt < 8; nt++) {
                int col = colBlk + wn * 64 + nt * 8 + tg * 2;
                float v0 = c[mt][nt][i * 2 + 0];
                float v1 = c[mt][nt][i * 2 + 1];
                if (bias) { v0 += bias[col]; v1 += bias[col + 1]; }
                if (act) { v0 = fmaxf(v0, 0.f); v1 = fmaxf(v1, 0.f); }
                *(__half2*)(Ch + (size_t)row * DH + col) = __floats2half2_rn(v0, v1);
            }
        }
    }
}

// ---------------- fused softmax + aggregation ----------------
// TWO warps per node, each owning 128 of 256 columns (uint2 gathers):
// same traffic, 2x loads in flight. 256 threads = 4 nodes/block.
__global__ __launch_bounds__(256) void k_fusedagg(
    const __half* __restrict__ h, const float* __restrict__ bias,
    __half* __restrict__ out, const float* __restrict__ gas,
    const float* __restrict__ gad, int N)
{
    int wid = threadIdx.x >> 5;
    int node = blockIdx.x * 4 + (wid >> 1);
    if (node >= N) return;
    int half = wid & 1;
    int lane = threadIdx.x & 31;
    int beg = g_rowptr[node], end = g_rowptr[node + 1];
    float adn = gad[node];

    // softmax stats (redundant across the warp pair; 4B gathers are cheap)
    float m = -1e30f, ssum = 0.f;
    for (int p = beg + lane; p < end; p += 32) {
        int s = g_perm[p];
        float v = gas[s] + adn;
        v = (v > 0.f) ? v : 0.2f * v;
        float mn = fmaxf(m, v);
        ssum = ssum * __expf(m - mn) + __expf(v - mn);
        m = mn;
    }
#pragma unroll
    for (int o = 16; o; o >>= 1) {
        float mo = __shfl_xor_sync(0xffffffffu, m, o);
        float so = __shfl_xor_sync(0xffffffffu, ssum, o);
        float mn = fmaxf(m, mo);
        ssum = ssum * __expf(m - mn) + so * __expf(mo - mn);
        m = mn;
    }
    float inv = 1.0f / (ssum + 1e-16f);

    float acc[4] = {0.f, 0.f, 0.f, 0.f};
    const __half* hh = h + half * 128;     // this warp's column half

    for (int c0 = beg; c0 < end; c0 += 32) {
        int p = c0 + lane;
        float al = 0.f;
        int s = 0;                 // invalid lanes: alpha 0, src 0 (harmless)
        if (p < end) {
            s = g_perm[p];
            float v = gas[s] + adn;
            v = (v > 0.f) ? v : 0.2f * v;
            al = __expf(v - m) * inv;
        }
        int cnt = min(32, end - c0);
        // groups of 8 edges: broadcast, then 8 independent 8B gathers in flight
        for (int j = 0; j < cnt; j += 8) {
            float aa[8]; int sx[8]; uint2 vv[8];
#pragma unroll
            for (int q = 0; q < 8; q++) {
                aa[q] = __shfl_sync(0xffffffffu, al, j + q);
                sx[q] = __shfl_sync(0xffffffffu, s, j + q);
            }
#pragma unroll
            for (int q = 0; q < 8; q++)
                vv[q] = ((const uint2*)(hh + (size_t)sx[q] * DH))[lane];
#pragma unroll
            for (int q = 0; q < 8; q++) {
                const __half2* hp = (const __half2*)&vv[q];
                float2 f0 = __half22float2(hp[0]);
                float2 f1 = __half22float2(hp[1]);
                float a = aa[q];
                acc[0] += a * f0.x; acc[1] += a * f0.y;
                acc[2] += a * f1.x; acc[3] += a * f1.y;
            }
        }
    }

    float4 bb = ((const float4*)(bias + half * 128))[lane];
    __half2 o0 = __floats2half2_rn(fmaxf(acc[0] + bb.x, 0.f), fmaxf(acc[1] + bb.y, 0.f));
    __half2 o1 = __floats2half2_rn(fmaxf(acc[2] + bb.z, 0.f), fmaxf(acc[3] + bb.w, 0.f));
    uint2 pack;
    pack.x = *(unsigned*)&o0; pack.y = *(unsigned*)&o1;
    ((uint2*)(out + (size_t)node * DH + half * 128))[lane] = pack;
}

// ---------------- final head: out = tanh(x @ Wm2 + bm2), 256 -> 8 (fp16 in) ----------------
__global__ __launch_bounds__(256) void k_mlp2(
    const __half* __restrict__ x, const float* __restrict__ W,
    const float* __restrict__ b, float* __restrict__ out, int N)
{
    __shared__ float wT[8][256];
    for (int i = threadIdx.x; i < 2048; i += 256) {
        int k = i >> 3, o = i & 7;
        wT[o][k] = W[i];
    }
    __syncthreads();
    int node = blockIdx.x * 8 + (threadIdx.x >> 5);
    if (node >= N) return;
    int lane = threadIdx.x & 31;
    const __half* row = x + (size_t)node * DH;
    float p[8] = {0, 0, 0, 0, 0, 0, 0, 0};
#pragma unroll
    for (int j = 0; j < 8; j++) {
        int k = lane + 32 * j;
        float xv = __half2float(row[k]);
#pragma unroll
        for (int o = 0; o < 8; o++) p[o] += xv * wT[o][k];
    }
#pragma unroll
    for (int o = 0; o < 8; o++)
#pragma unroll
        for (int off = 16; off; off >>= 1)
            p[o] += __shfl_xor_sync(0xffffffffu, p[o], off);
    if (lane < 8) {
        float v = p[0];
#pragma unroll
        for (int o = 1; o < 8; o++) if (lane == o) v = p[o];
        out[(size_t)node * AOUT + lane] = tanhf(v + b[lane]);
    }
}

// ---------------- launch ----------------
extern "C" void kernel_launch(void* const* d_in, const int* in_sizes, int n_in,
                              void* d_out, int out_size)
{
    const float* obs = (const float*)d_in[0];
    const int*   ei  = (const int*)d_in[1];
    const float* W1  = (const float*)d_in[2];
    const float* a1s = (const float*)d_in[3];
    const float* a1d = (const float*)d_in[4];
    const float* b1  = (const float*)d_in[5];
    const float* W2  = (const float*)d_in[6];
    const float* a2s = (const float*)d_in[7];
    const float* a2d = (const float*)d_in[8];
    const float* b2  = (const float*)d_in[9];
    const float* Wm1 = (const float*)d_in[10];
    const float* bm1 = (const float*)d_in[11];
    const float* Wm2 = (const float*)d_in[12];
    const float* bm2 = (const float*)d_in[13];
    float* out = (float*)d_out;

    const int N  = in_sizes[0] / DH;
    const int E  = in_sizes[1] / 2;
    const int NB = (N + SCANB - 1) / SCANB;   // scan blocks (<=128)

    __half *obsh, *h1, *h2, *w1h, *w2h, *wm1h;
    float *as1, *ad1, *as2, *ad2;
    cudaGetSymbolAddress((void**)&obsh, g_obsh);
    cudaGetSymbolAddress((void**)&h1,   g_h1);
    cudaGetSymbolAddress((void**)&h2,   g_h2);
    cudaGetSymbolAddress((void**)&w1h,  g_w1h);
    cudaGetSymbolAddress((void**)&w2h,  g_w2h);
    cudaGetSymbolAddress((void**)&wm1h, g_wm1h);
    cudaGetSymbolAddress((void**)&as1,  g_as1);
    cudaGetSymbolAddress((void**)&ad1,  g_ad1);
    cudaGetSymbolAddress((void**)&as2,  g_as2);
    cudaGetSymbolAddress((void**)&ad2,  g_ad2);

    cudaFuncSetAttribute(k_gemm_f16, cudaFuncAttributeMaxDynamicSharedMemorySize, SMEM_GEMM);

    cudaStream_t s2;
    cudaEvent_t evFork, evCsr;
    cudaStreamCreateWithFlags(&s2, cudaStreamNonBlocking);
    cudaEventCreateWithFlags(&evFork, cudaEventDisableTiming);
    cudaEventCreateWithFlags(&evCsr, cudaEventDisableTiming);

    const int T = 256;
    dim3 gemmGrid(DH / GBN, (N + GBM - 1) / GBM);   // (2, 313)
    int nodeBlocks4 = (N + 3) / 4;     // fusedagg: 4 nodes/block (2 warps each)
    int nodeBlocks8 = (N + 7) / 8;     // mlp2: 8 nodes/block
    int scat4Blocks = ((E + 3) / 4 + T - 1) / T;
    int obs8 = N * DH / 8;
    int prepTotal = 3 * 65536 + N + obs8;

    // legal capture fork: record on main FIRST, then s2 waits on it.
    cudaEventRecord(evFork, 0);
    cudaStreamWaitEvent(s2, evFork, 0);

    // side chain head: zero -> count
    k_zero<<<(N + T - 1) / T, T, 0, s2>>>(N);                 // enqueue 1
    k_count<<<(E / 4 + T - 1) / T, T, 0, s2>>>(ei, E);        // enqueue 2
    // main: merged prep, then GAT layer-1 GEMM (enqueue 4 -> ncu-profiled)
    k_prep<<<(prepTotal + T - 1) / T, T>>>(W1, W2, Wm1, obs, N, obs8);  // 3
    k_gemm_f16<<<gemmGrid, 128, SMEM_GEMM>>>(obsh, w1h, h1, N,          // 4
                                             nullptr, 0, a1s, a1d, as1, ad1);
    // side chain tail: scan1/2/3 + scatter
    k_scan1<<<NB, SCANB, 0, s2>>>(N);                         // 5
    k_scan2<<<1, 128, 0, s2>>>(NB);                           // 6
    k_scan3<<<NB, SCANB, 0, s2>>>(N);                         // 7
    k_scatter<<<scat4Blocks, T, 0, s2>>>(ei, E);              // 8
    cudaEventRecord(evCsr, s2);
    cudaStreamWaitEvent(0, evCsr, 0);

    // layer-1 softmax+aggregate (fp16 out -> gemm2 input)
    k_fusedagg<<<nodeBlocks4, T>>>(h1, b1, h2, as1, ad1, N);
    // GAT layer 2
    k_gemm_f16<<<gemmGrid, 128, SMEM_GEMM>>>(h2, w2h, h1, N,
                                             nullptr, 0, a2s, a2d, as2, ad2);
    k_fusedagg<<<nodeBlocks4, T>>>(h1, b2, h2, as2, ad2, N);
    // MLP layer 1 (relu + bm1, fp16 out into obsh)
    k_gemm_f16<<<gemmGrid, 128, SMEM_GEMM>>>(h2, wm1h, obsh, N,
                                             bm1, 1, nullptr, nullptr, nullptr, nullptr);
    // final head (fp16 input)
    k_mlp2<<<nodeBlocks8, T>>>(obsh, Wm2, bm2, out, N);
}

// round 17
// speedup vs baseline: 1.1304x; 1.1304x over previous
#include <cuda_runtime.h>
#include <cuda_fp16.h>
#include <math.h>

#define DH 256          // feature dim (D == H == 256)
#define AOUT 8
#define MAXN 20000
#define MAXE 320000
#define MAXT (MAXN + MAXE)
#define SCANB 256       // scan1/scan3 block size

// ---------------- device scratch (no allocations allowed) ----------------
__device__ __half   g_obsh[(size_t)MAXN * DH];   // fp16 obs; reused as gemm3 out
__device__ __half   g_h1[(size_t)MAXN * DH];     // gemm outputs (fp16)
__device__ __half   g_h2[(size_t)MAXN * DH];
__device__ __half   g_w1h[DH * DH];              // weights, fp16, TRANSPOSED [n][k]
__device__ __half   g_w2h[DH * DH];
__device__ __half   g_wm1h[DH * DH];
__device__ float    g_as1[MAXN];
__device__ float    g_ad1[MAXN];
__device__ float    g_as2[MAXN];
__device__ float    g_ad2[MAXN];
__device__ float    g_ew[MAXT];           // per-edge scores (pass1 -> pass2)
__device__ int      g_rowptr[MAXN + 1];
__device__ int      g_cursor[MAXN];
__device__ int      g_partial[MAXN];      // exclusive within-block prefixes
__device__ int      g_blocksums[128];
__device__ int      g_blockoff[128];
__device__ int      g_perm[MAXT];         // src node ids grouped by dst

// ---------------- prep: weights->fp16^T, score-acc zeros, obs->fp16 ----------------
__global__ void k_prep(const float* __restrict__ W1,
                       const float* __restrict__ W2,
                       const float* __restrict__ Wm1,
                       const float* __restrict__ obs,
                       int N, int obs8)
{
    int i = blockIdx.x * blockDim.x + threadIdx.x;
    if (i < 65536) {
        int n = i >> 8, k = i & 255;                 // write coalesced in [n][k]
        g_w1h[i] = __float2half(W1[k * DH + n]);
    } else if (i < 2 * 65536) {
        int j = i - 65536;
        int n = j >> 8, k = j & 255;
        g_w2h[j] = __float2half(W2[k * DH + n]);
    } else if (i < 3 * 65536) {
        int j = i - 2 * 65536;
        int n = j >> 8, k = j & 255;
        g_wm1h[j] = __float2half(Wm1[k * DH + n]);
    } else if (i < 3 * 65536 + N) {
        int j = i - 3 * 65536;
        g_as1[j] = 0.f; g_ad1[j] = 0.f;
        g_as2[j] = 0.f; g_ad2[j] = 0.f;
    } else {
        int q = i - 3 * 65536 - N;
        if (q < obs8) {
            const float4* src = (const float4*)(obs) + q * 2;
            float4 v0 = src[0], v1 = src[1];
            __half2 h0 = __floats2half2_rn(v0.x, v0.y);
            __half2 h1 = __floats2half2_rn(v0.z, v0.w);
            __half2 h2 = __floats2half2_rn(v1.x, v1.y);
            __half2 h3 = __floats2half2_rn(v1.z, v1.w);
            uint4 pack;
            pack.x = *(unsigned*)&h0; pack.y = *(unsigned*)&h1;
            pack.z = *(unsigned*)&h2; pack.w = *(unsigned*)&h3;
            ((uint4*)g_obsh)[q] = pack;
        }
    }
}

// ---------------- CSR build (self-loops handled implicitly) ----------------
__global__ void k_zero(int N) {
    int i = blockIdx.x * blockDim.x + threadIdx.x;
    if (i < N) g_cursor[i] = 0;
}

__global__ void k_count(const int* __restrict__ ei, int E) {
    int q = blockIdx.x * blockDim.x + threadIdx.x;
    if (q * 4 >= E) return;
    int4 d4 = *(const int4*)(ei + E + q * 4);
    atomicAdd(&g_cursor[d4.x], 1);
    atomicAdd(&g_cursor[d4.y], 1);
    atomicAdd(&g_cursor[d4.z], 1);
    atomicAdd(&g_cursor[d4.w], 1);
}

// two-level scan: scan1 per-block, scan2 block sums, scan3 emit
__global__ void k_scan1(int N) {
    int i = blockIdx.x * SCANB + threadIdx.x;
    int v = (i < N) ? (g_cursor[i] + 1) : 0;      // +1 self-loop
    int lane = threadIdx.x & 31, w = threadIdx.x >> 5;
    int x = v;
#pragma unroll
    for (int o = 1; o < 32; o <<= 1) {
        int t = __shfl_up_sync(0xffffffffu, x, o);
        if (lane >= o) x += t;
    }
    __shared__ int wsum[8];
    if (lane == 31) wsum[w] = x;
    __syncthreads();
    if (w == 0) {
        int y = (lane < 8) ? wsum[lane] : 0;
#pragma unroll
        for (int o = 1; o < 8; o <<= 1) {
            int t = __shfl_up_sync(0xffffffffu, y, o);
            if (lane >= o) y += t;
        }
        if (lane < 8) wsum[lane] = y;
    }
    __syncthreads();
    int incl = x + (w > 0 ? wsum[w - 1] : 0);
    if (i < N) g_partial[i] = incl - v;           // exclusive prefix in block
    if (threadIdx.x == SCANB - 1) g_blocksums[blockIdx.x] = incl;
}

__global__ void k_scan2(int nb) {   // 1 block, 128 threads; nb <= 128
    int tid = threadIdx.x;
    int v = (tid < nb) ? g_blocksums[tid] : 0;
    int lane = tid & 31, w = tid >> 5;
    int x = v;
#pragma unroll
    for (int o = 1; o < 32; o <<= 1) {
        int t = __shfl_up_sync(0xffffffffu, x, o);
        if (lane >= o) x += t;
    }
    __shared__ int ws[4];
    if (lane == 31) ws[w] = x;
    __syncthreads();
    if (w == 0) {
        int y = (lane < 4) ? ws[lane] : 0;
#pragma unroll
        for (int o = 1; o < 4; o <<= 1) {
            int t = __shfl_up_sync(0xffffffffu, y, o);
            if (lane >= o) y += t;
        }
        if (lane < 4) ws[lane] = y;
    }
    __syncthreads();
    int incl = x + (w > 0 ? ws[w - 1] : 0);
    if (tid < nb) g_blockoff[tid] = incl - v;     // exclusive block offset
}

__global__ void k_scan3(int N) {
    int i = blockIdx.x * SCANB + threadIdx.x;
    if (i >= N) return;
    int c = g_cursor[i];                          // original degree
    int run = g_partial[i] + g_blockoff[blockIdx.x];
    g_rowptr[i] = run;
    g_perm[run] = i;                              // self-loop at group head
    g_cursor[i] = run + 1;                        // scatter cursor
    if (i == N - 1) g_rowptr[N] = run + c + 1;
}

__global__ void k_scatter(const int* __restrict__ ei, int E) {
    int e = blockIdx.x * blockDim.x + threadIdx.x;
    if (e >= E) return;
    int s = ei[e], d = ei[E + e];
    int pos = atomicAdd(&g_cursor[d], 1);
    g_perm[pos] = s;
}

// ---------------- fp16 tensor-core GEMM: C[M,256] = A[M,256] @ B^T ----------------
// A fp16 [M][K] row-major; B fp16 [N][K] row-major (pre-transposed weights).
// CTA 64x128, BK=32, 4 warps (each 32x64), mma.m16n8k16, ldmatrix fragment loads.
#define GBM 64
#define GBN 128
#define GBK 32
#define ASTRH 40     // 32 + 8 pad halves (80B row; ldmatrix conflict-free)
#define BSTRH 40
#define ASZH (GBM * ASTRH)     // 2560 halves
#define BSZH (GBN * BSTRH)     // 5120 halves
#define NSTAGE 3
#define SMEM_GEMM (NSTAGE * (ASZH + BSZH) * 2)   // 46080 bytes

__global__ __launch_bounds__(128, 4) void k_gemm_f16(
    const __half* __restrict__ A, const __half* __restrict__ Bt,
    __half* __restrict__ Ch, int M,
    const float* __restrict__ bias, int act,
    const float* __restrict__ asrc, const float* __restrict__ adst,
    float* as_out, float* ad_out)
{
    extern __shared__ __half smh[];
    __half* As = smh;                      // [NSTAGE][GBM][ASTRH]
    __half* Bs = smh + NSTAGE * ASZH;      // [NSTAGE][GBN][BSTRH]

    const int tid = threadIdx.x;
    const int warpId = tid >> 5, lane = tid & 31;
    const int gid = lane >> 2, tg = lane & 3;
    const int wm = warpId >> 1, wn = warpId & 1;    // 2x2 warp grid
    const int rowBlk = blockIdx.y * GBM;
    const int colBlk = blockIdx.x * GBN;

    const int l7 = lane & 7;
    const int sel8  = (lane & 8)  ? 8 : 0;
    const int sel16 = (lane & 16) ? 8 : 0;

    float c[2][8][4];
#pragma unroll
    for (int mt = 0; mt < 2; mt++)
#pragma unroll
        for (int nt = 0; nt < 8; nt++)
#pragma unroll
            for (int q = 0; q < 4; q++) c[mt][nt][q] = 0.f;

    auto issue = [&](int buf, int k0) {
#pragma unroll
        for (int i = 0; i < 2; i++) {           // A: 64 rows x 4 chunks(16B)
            int f = tid + i * 128;
            int r = f >> 2, ch = (f & 3) << 3;
            int grow = rowBlk + r;
            const __half* src = A + (size_t)grow * DH + k0 + ch;
            unsigned dst = (unsigned)__cvta_generic_to_shared(&As[buf * ASZH + r * ASTRH + ch]);
            int sz = (grow < M) ? 16 : 0;
            asm volatile("cp.async.cg.shared.global [%0], [%1], 16, %2;\n"
                         :: "r"(dst), "l"(src), "r"(sz));
        }
#pragma unroll
        for (int i = 0; i < 4; i++) {           // B: 128 rows(n) x 4 chunks
            int f = tid + i * 128;
            int n = f >> 2, ch = (f & 3) << 3;
            const __half* src = Bt + (size_t)(colBlk + n) * DH + k0 + ch;
            unsigned dst = (unsigned)__cvta_generic_to_shared(&Bs[buf * BSZH + n * BSTRH + ch]);
            asm volatile("cp.async.cg.shared.global [%0], [%1], 16;\n"
                         :: "r"(dst), "l"(src));
        }
        asm volatile("cp.async.commit_group;\n");
    };

    auto compute = [&](int buf) {
        unsigned a[2][2][4];
#pragma unroll
        for (int ks = 0; ks < 2; ks++) {
            const int kk = ks * 16;
#pragma unroll
            for (int mt = 0; mt < 2; mt++) {
                int row = wm * 32 + mt * 16 + l7 + sel8;
                unsigned ad = (unsigned)__cvta_generic_to_shared(
                    &As[buf * ASZH + row * ASTRH + kk + sel16]);
                asm volatile(
                    "ldmatrix.sync.aligned.m8n8.x4.shared.b16 {%0,%1,%2,%3}, [%4];\n"
                    : "=r"(a[ks][mt][0]), "=r"(a[ks][mt][1]),
                      "=r"(a[ks][mt][2]), "=r"(a[ks][mt][3])
                    : "r"(ad));
            }
        }
#pragma unroll
        for (int ks = 0; ks < 2; ks++) {
            const int kk = ks * 16;
            unsigned b[8][2];
#pragma unroll
            for (int p = 0; p < 4; p++) {
                int nrow = wn * 64 + p * 16 + sel16 + l7;
                unsigned ad = (unsigned)__cvta_generic_to_shared(
                    &Bs[buf * BSZH + nrow * BSTRH + kk + sel8]);
                asm volatile(
                    "ldmatrix.sync.aligned.m8n8.x4.shared.b16 {%0,%1,%2,%3}, [%4];\n"
                    : "=r"(b[2 * p][0]), "=r"(b[2 * p][1]),
                      "=r"(b[2 * p + 1][0]), "=r"(b[2 * p + 1][1])
                    : "r"(ad));
            }
#pragma unroll
            for (int mt = 0; mt < 2; mt++)
#pragma unroll
                for (int nt = 0; nt < 8; nt++)
                    asm volatile(
                        "mma.sync.aligned.m16n8k16.row.col.f32.f16.f16.f32 "
                        "{%0,%1,%2,%3}, {%4,%5,%6,%7}, {%8,%9}, {%0,%1,%2,%3};\n"
                        : "+f"(c[mt][nt][0]), "+f"(c[mt][nt][1]),
                          "+f"(c[mt][nt][2]), "+f"(c[mt][nt][3])
                        : "r"(a[ks][mt][0]), "r"(a[ks][mt][1]),
                          "r"(a[ks][mt][2]), "r"(a[ks][mt][3]),
                          "r"(b[nt][0]), "r"(b[nt][1]));
        }
    };

    issue(0, 0);
    issue(1, GBK);
#pragma unroll
    for (int it = 0; it < DH / GBK; it++) {
        if (it < DH / GBK - 1)
            asm volatile("cp.async.wait_group 1;\n");
        else
            asm volatile("cp.async.wait_group 0;\n");
        __syncthreads();
        if (it + 2 < DH / GBK) issue((it + 2) % NSTAGE, (it + 2) * GBK);
        compute(it % NSTAGE);
    }

    // ---- fused attention scores (layers 1 & 2; fp32 accumulators) ----
    if (asrc) {
#pragma unroll
        for (int mt = 0; mt < 2; mt++) {
#pragma unroll
            for (int i = 0; i < 2; i++) {
                float s = 0.f, d = 0.f;
#pragma unroll
                for (int nt = 0; nt < 8; nt++) {
                    int col = colBlk + wn * 64 + nt * 8 + tg * 2;
                    s += c[mt][nt][i * 2] * asrc[col] + c[mt][nt][i * 2 + 1] * asrc[col + 1];
                    d += c[mt][nt][i * 2] * adst[col] + c[mt][nt][i * 2 + 1] * adst[col + 1];
                }
                s += __shfl_xor_sync(0xffffffffu, s, 1);
                s += __shfl_xor_sync(0xffffffffu, s, 2);
                d += __shfl_xor_sync(0xffffffffu, d, 1);
                d += __shfl_xor_sync(0xffffffffu, d, 2);
                int row = rowBlk + wm * 32 + mt * 16 + gid + i * 8;
                if (tg == 0 && row < M) {
                    atomicAdd(&as_out[row], s);
                    atomicAdd(&ad_out[row], d);
                }
            }
        }
    }

    // ---- store C (fp16) ----
#pragma unroll
    for (int mt = 0; mt < 2; mt++) {
#pragma unroll
        for (int i = 0; i < 2; i++) {
            int row = rowBlk + wm * 32 + mt * 16 + gid + i * 8;
            if (row >= M) continue;
#pragma unroll
            for (int nt = 0; nt < 8; nt++) {
                int col = colBlk + wn * 64 + nt * 8 + tg * 2;
                float v0 = c[mt][nt][i * 2 + 0];
                float v1 = c[mt][nt][i * 2 + 1];
                if (bias) { v0 += bias[col]; v1 += bias[col + 1]; }
                if (act) { v0 = fmaxf(v0, 0.f); v1 = fmaxf(v1, 0.f); }
                *(__half2*)(Ch + (size_t)row * DH + col) = __floats2half2_rn(v0, v1);
            }
        }
    }
}

// ---------------- fused softmax + aggregation (warp per node, fp16, 4x MLP) ----------------
// Pass 1 writes per-edge scores to g_ew (coalesced); pass 2 reads them back
// coalesced instead of redoing the random gas[perm[p]] gather.
__global__ __launch_bounds__(256) void k_fusedagg(
    const __half* __restrict__ h, const float* __restrict__ bias,
    __half* __restrict__ out, const float* __restrict__ gas,
    const float* __restrict__ gad, int N)
{
    int node = blockIdx.x * 8 + (threadIdx.x >> 5);
    if (node >= N) return;
    int lane = threadIdx.x & 31;
    int beg = g_rowptr[node], end = g_rowptr[node + 1];
    float adn = gad[node];

    // pass 1: stats + stash scores
    float m = -1e30f, ssum = 0.f;
    for (int p = beg + lane; p < end; p += 32) {
        int s = g_perm[p];
        float v = gas[s] + adn;
        v = (v > 0.f) ? v : 0.2f * v;
        g_ew[p] = v;                               // coalesced stash
        float mn = fmaxf(m, v);
        ssum = ssum * __expf(m - mn) + __expf(v - mn);
        m = mn;
    }
#pragma unroll
    for (int o = 16; o; o >>= 1) {
        float mo = __shfl_xor_sync(0xffffffffu, m, o);
        float so = __shfl_xor_sync(0xffffffffu, ssum, o);
        float mn = fmaxf(m, mo);
        ssum = ssum * __expf(m - mn) + so * __expf(mo - mn);
        m = mn;
    }
    float inv = 1.0f / (ssum + 1e-16f);

    float acc[8];
#pragma unroll
    for (int q = 0; q < 8; q++) acc[q] = 0.f;

    __syncwarp();
    for (int c0 = beg; c0 < end; c0 += 32) {
        int p = c0 + lane;
        float al = 0.f;
        int s = 0;                 // invalid lanes: alpha 0, src 0 (harmless)
        if (p < end) {
            s = g_perm[p];
            al = __expf(g_ew[p] - m) * inv;        // coalesced reload
        }
        int cnt = min(32, end - c0);
        // groups of 4 edges: broadcast, then 4 independent gathers in flight
        for (int j = 0; j < cnt; j += 4) {
            float aa[4]; int sx[4]; uint4 vv[4];
#pragma unroll
            for (int q = 0; q < 4; q++) {
                aa[q] = __shfl_sync(0xffffffffu, al, j + q);
                sx[q] = __shfl_sync(0xffffffffu, s, j + q);
            }
#pragma unroll
            for (int q = 0; q < 4; q++)
                vv[q] = ((const uint4*)(h + (size_t)sx[q] * DH))[lane];
#pragma unroll
            for (int q = 0; q < 4; q++) {
                const __half2* hp = (const __half2*)&vv[q];
                float2 f0 = __half22float2(hp[0]);
                float2 f1 = __half22float2(hp[1]);
                float2 f2 = __half22float2(hp[2]);
                float2 f3 = __half22float2(hp[3]);
                float a = aa[q];
                acc[0] += a * f0.x; acc[1] += a * f0.y;
                acc[2] += a * f1.x; acc[3] += a * f1.y;
                acc[4] += a * f2.x; acc[5] += a * f2.y;
                acc[6] += a * f3.x; acc[7] += a * f3.y;
            }
        }
    }

    float4 b0 = ((const float4*)bias)[lane * 2];
    float4 b1 = ((const float4*)bias)[lane * 2 + 1];
    __half2 h0 = __floats2half2_rn(fmaxf(acc[0] + b0.x, 0.f), fmaxf(acc[1] + b0.y, 0.f));
    __half2 h1 = __floats2half2_rn(fmaxf(acc[2] + b0.z, 0.f), fmaxf(acc[3] + b0.w, 0.f));
    __half2 h2 = __floats2half2_rn(fmaxf(acc[4] + b1.x, 0.f), fmaxf(acc[5] + b1.y, 0.f));
    __half2 h3 = __floats2half2_rn(fmaxf(acc[6] + b1.z, 0.f), fmaxf(acc[7] + b1.w, 0.f));
    uint4 pack;
    pack.x = *(unsigned*)&h0; pack.y = *(unsigned*)&h1;
    pack.z = *(unsigned*)&h2; pack.w = *(unsigned*)&h3;
    *(uint4*)(out + (size_t)node * DH + lane * 8) = pack;
}

// ---------------- final head: out = tanh(x @ Wm2 + bm2), 256 -> 8 (fp16 in) ----------------
__global__ __launch_bounds__(256) void k_mlp2(
    const __half* __restrict__ x, const float* __restrict__ W,
    const float* __restrict__ b, float* __restrict__ out, int N)
{
    __shared__ float wT[8][256];
    for (int i = threadIdx.x; i < 2048; i += 256) {
        int k = i >> 3, o = i & 7;
        wT[o][k] = W[i];
    }
    __syncthreads();
    int node = blockIdx.x * 8 + (threadIdx.x >> 5);
    if (node >= N) return;
    int lane = threadIdx.x & 31;
    const __half* row = x + (size_t)node * DH;
    float p[8] = {0, 0, 0, 0, 0, 0, 0, 0};
#pragma unroll
    for (int j = 0; j < 8; j++) {
        int k = lane + 32 * j;
        float xv = __half2float(row[k]);
#pragma unroll
        for (int o = 0; o < 8; o++) p[o] += xv * wT[o][k];
    }
#pragma unroll
    for (int o = 0; o < 8; o++)
#pragma unroll
        for (int off = 16; off; off >>= 1)
            p[o] += __shfl_xor_sync(0xffffffffu, p[o], off);
    if (lane < 8) {
        float v = p[0];
#pragma unroll
        for (int o = 1; o < 8; o++) if (lane == o) v = p[o];
        out[(size_t)node * AOUT + lane] = tanhf(v + b[lane]);
    }
}

// ---------------- launch ----------------
extern "C" void kernel_launch(void* const* d_in, const int* in_sizes, int n_in,
                              void* d_out, int out_size)
{
    const float* obs = (const float*)d_in[0];
    const int*   ei  = (const int*)d_in[1];
    const float* W1  = (const float*)d_in[2];
    const float* a1s = (const float*)d_in[3];
    const float* a1d = (const float*)d_in[4];
    const float* b1  = (const float*)d_in[5];
    const float* W2  = (const float*)d_in[6];
    const float* a2s = (const float*)d_in[7];
    const float* a2d = (const float*)d_in[8];
    const float* b2  = (const float*)d_in[9];
    const float* Wm1 = (const float*)d_in[10];
    const float* bm1 = (const float*)d_in[11];
    const float* Wm2 = (const float*)d_in[12];
    const float* bm2 = (const float*)d_in[13];
    float* out = (float*)d_out;

    const int N  = in_sizes[0] / DH;
    const int E  = in_sizes[1] / 2;
    const int NB = (N + SCANB - 1) / SCANB;   // scan blocks (<=128)

    __half *obsh, *h1, *h2, *w1h, *w2h, *wm1h;
    float *as1, *ad1, *as2, *ad2;
    cudaGetSymbolAddress((void**)&obsh, g_obsh);
    cudaGetSymbolAddress((void**)&h1,   g_h1);
    cudaGetSymbolAddress((void**)&h2,   g_h2);
    cudaGetSymbolAddress((void**)&w1h,  g_w1h);
    cudaGetSymbolAddress((void**)&w2h,  g_w2h);
    cudaGetSymbolAddress((void**)&wm1h, g_wm1h);
    cudaGetSymbolAddress((void**)&as1,  g_as1);
    cudaGetSymbolAddress((void**)&ad1,  g_ad1);
    cudaGetSymbolAddress((void**)&as2,  g_as2);
    cudaGetSymbolAddress((void**)&ad2,  g_ad2);

    cudaFuncSetAttribute(k_gemm_f16, cudaFuncAttributeMaxDynamicSharedMemorySize, SMEM_GEMM);

    cudaStream_t s2;
    cudaEvent_t evFork, evCsr;
    cudaStreamCreateWithFlags(&s2, cudaStreamNonBlocking);
    cudaEventCreateWithFlags(&evFork, cudaEventDisableTiming);
    cudaEventCreateWithFlags(&evCsr, cudaEventDisableTiming);

    const int T = 256;
    dim3 gemmGrid(DH / GBN, (N + GBM - 1) / GBM);   // (2, 313)
    int nodeBlocks = (N + 7) / 8;
    int edgeBlocks = (E + T - 1) / T;
    int obs8 = N * DH / 8;
    int prepTotal = 3 * 65536 + N + obs8;

    // legal capture fork: record on main FIRST, then s2 waits on it.
    cudaEventRecord(evFork, 0);
    cudaStreamWaitEvent(s2, evFork, 0);

    // side chain: zero -> count -> scan1 -> scan2 -> scan3 -> scatter
    k_zero<<<(N + T - 1) / T, T, 0, s2>>>(N);
    k_count<<<(E / 4 + T - 1) / T, T, 0, s2>>>(ei, E);
    // main: merged prep (weights^T->fp16, score-acc zeros, obs->fp16)
    k_prep<<<(prepTotal + T - 1) / T, T>>>(W1, W2, Wm1, obs, N, obs8);
    k_scan1<<<NB, SCANB, 0, s2>>>(N);
    k_scan2<<<1, 128, 0, s2>>>(NB);
    k_scan3<<<NB, SCANB, 0, s2>>>(N);
    k_scatter<<<edgeBlocks, T, 0, s2>>>(ei, E);
    cudaEventRecord(evCsr, s2);

    // main: GAT layer-1 GEMM — overlaps side chain
    k_gemm_f16<<<gemmGrid, 128, SMEM_GEMM>>>(obsh, w1h, h1, N,
                                             nullptr, 0, a1s, a1d, as1, ad1);
    cudaStreamWaitEvent(0, evCsr, 0);

    // layer-1 softmax+aggregate (fp16 out -> gemm2 input)
    k_fusedagg<<<nodeBlocks, T>>>(h1, b1, h2, as1, ad1, N);
    // GAT layer 2
    k_gemm_f16<<<gemmGrid, 128, SMEM_GEMM>>>(h2, w2h, h1, N,
                                             nullptr, 0, a2s, a2d, as2, ad2);
    k_fusedagg<<<nodeBlocks, T>>>(h1, b2, h2, as2, ad2, N);
    // MLP layer 1 (relu + bm1, fp16 out into obsh)
    k_gemm_f16<<<gemmGrid, 128, SMEM_GEMM>>>(h2, wm1h, obsh, N,
                                             bm1, 1, nullptr, nullptr, nullptr, nullptr);
    // final head (fp16 input)
    k_mlp2<<<nodeBlocks, T>>>(obsh, Wm2, bm2, out, N);
}